// round 2
// baseline (speedup 1.0000x reference)
#include <cuda_runtime.h>
#include <math.h>

#define BN 16
#define CN 256
#define NN 4096
#define KN 4
#define HN 512
#define SCALE 0.0625f   // 256^-0.5

// ---------------- scratch (device globals; no allocation) ----------------
__device__ float g_slots[BN*KN*CN];
__device__ float g_qkg  [BN*KN*CN];   // a[k][c] = scale*qk[c]*ln_in_g[c]
__device__ float g_G    [BN*KN];      // sum_c a
__device__ float g_off  [BN*KN];      // scale*(sum qk*ln_in_b + q.bk)
__device__ float g_S    [BN*KN];      // sum_n attn
__device__ float g_U    [BN*KN];      // sum_n attn*rs*m
__device__ float g_Araw [BN*KN*CN];   // sum_n (attn*rs)*x[c,n]
__device__ float g_mean [BN*NN];
__device__ float g_rstd [BN*NN];

// 256-thread dual block reduction; red must hold >=16 floats; leaves red reusable.
__device__ __forceinline__ void blockReduce2(float& a, float& b, float* red) {
    #pragma unroll
    for (int o = 16; o; o >>= 1) {
        a += __shfl_down_sync(0xffffffffu, a, o);
        b += __shfl_down_sync(0xffffffffu, b, o);
    }
    int w = threadIdx.x >> 5;
    if ((threadIdx.x & 31) == 0) { red[w] = a; red[8 + w] = b; }
    __syncthreads();
    a = red[0]+red[1]+red[2]+red[3]+red[4]+red[5]+red[6]+red[7];
    b = red[8]+red[9]+red[10]+red[11]+red[12]+red[13]+red[14]+red[15];
    __syncthreads();
}

// ---------------- init: slots = mu + exp(log_sigma)*noise ----------------
__global__ void k_init(const float* __restrict__ noise, const float* __restrict__ mu,
                       const float* __restrict__ lsig) {
    int r = blockIdx.x, c = threadIdx.x;
    g_slots[r*CN + c] = mu[c] + expf(lsig[c]) * noise[r*CN + c];
}

// ---------------- per-iteration slot prep: LN, q, folded a/G/off; zero accums ---
__global__ void __launch_bounds__(256) k_prep(
    const float* __restrict__ Wq, const float* __restrict__ bq,
    const float* __restrict__ Wk, const float* __restrict__ bk,
    const float* __restrict__ lsg, const float* __restrict__ lsb,
    const float* __restrict__ lig, const float* __restrict__ lib)
{
    __shared__ __align__(16) float sv[CN];
    __shared__ __align__(16) float sq[CN];
    __shared__ float red[16];
    int r = blockIdx.x, tid = threadIdx.x;

    float v = g_slots[r*CN + tid];
    float s1 = v, s2 = v*v;
    blockReduce2(s1, s2, red);
    float mean = s1 * (1.0f/CN);
    float var  = s2 * (1.0f/CN) - mean*mean;
    float rstd = rsqrtf(var + 1e-5f);
    sv[tid] = (v - mean) * rstd * lsg[tid] + lsb[tid];
    __syncthreads();

    // q[d] = sum_c sv[c]*Wq[d,c] + bq[d]
    float q0 = 0.f, q1 = 0.f;
    {
        const float4* wq4 = (const float4*)(Wq + tid*CN);
        const float4* sv4 = (const float4*)sv;
        #pragma unroll 8
        for (int i = 0; i < CN/4; i += 2) {
            float4 w = wq4[i],   xx = sv4[i];
            q0 += w.x*xx.x + w.y*xx.y + w.z*xx.z + w.w*xx.w;
            float4 w2 = wq4[i+1], x2 = sv4[i+1];
            q1 += w2.x*x2.x + w2.y*x2.y + w2.z*x2.z + w2.w*x2.w;
        }
    }
    float qd = q0 + q1 + bq[tid];
    sq[tid] = qd;
    float qb = qd * bk[tid];
    float dummy = 0.f;
    __syncthreads();
    blockReduce2(qb, dummy, red);

    // qk[c] = sum_d q[d]*Wk[d,c]   (coalesced across threads)
    float a0=0.f,a1=0.f,a2=0.f,a3=0.f;
    #pragma unroll 4
    for (int d = 0; d < CN; d += 4) {
        a0 += sq[d+0]*Wk[(d+0)*CN + tid];
        a1 += sq[d+1]*Wk[(d+1)*CN + tid];
        a2 += sq[d+2]*Wk[(d+2)*CN + tid];
        a3 += sq[d+3]*Wk[(d+3)*CN + tid];
    }
    float qkc = (a0+a1) + (a2+a3);
    float av  = SCALE * qkc * lig[tid];
    g_qkg[r*CN + tid] = av;
    float offp = SCALE * qkc * lib[tid];
    float Gs = av;
    blockReduce2(Gs, offp, red);
    if (tid == 0) {
        g_G[r]   = Gs;
        g_off[r] = offp + SCALE * qb;
        g_S[r]   = 0.f;
        g_U[r]   = 0.f;
    }
    g_Araw[r*CN + tid] = 0.f;
}

// ---------------- main attention pass ----------------
// grid (32, 16) : tile t (128 pixels) x batch b. 256 threads.
__global__ void __launch_bounds__(256) k_attn(const float* __restrict__ x, int first) {
    extern __shared__ float sm[];
    float* xs  = sm;               // [256][129]
    float* sa  = xs  + 256*129;    // [4][256]
    float* sd  = sa  + 1024;       // [8][4][128] dot partials ; reused as [2][4][256]
    float* sst = sd  + 4096;       // [8][2][128] stats partials (iter0)
    float* tvv = sst + 2048;       // [4][128]  t_k = attn*rs
    float* smr = tvv + 512;        // [2][128]  m, rs (iter>0)
    float* sc  = smr + 256;        // G[4], off[4]

    int b = blockIdx.y, t = blockIdx.x, tid = threadIdx.x;
    int n0 = t * 128;

    for (int i = tid; i < 1024; i += 256) sa[i] = g_qkg[b*1024 + i];
    if (tid < 4) { sc[tid] = g_G[b*4 + tid]; sc[4+tid] = g_off[b*4 + tid]; }
    if (!first && tid < 128) {
        smr[tid]       = g_mean[b*NN + n0 + tid];
        smr[128 + tid] = g_rstd[b*NN + n0 + tid];
    }
    const float* xb = x + (size_t)b*CN*NN + n0;
    for (int i = tid; i < 256*128; i += 256) {
        int c = i >> 7, p = i & 127;
        xs[c*129 + p] = xb[c*4096 + p];
    }
    __syncthreads();

    // ---- phase 1: dots (and stats on iter 0) ----
    {
        int pg = tid & 31, ch = tid >> 5;
        float acc[4][4];
        #pragma unroll
        for (int k = 0; k < 4; k++)
            #pragma unroll
            for (int j = 0; j < 4; j++) acc[k][j] = 0.f;

        int cbase = ch * 32;
        if (first) {
            float sx[4] = {0,0,0,0}, sxx[4] = {0,0,0,0};
            #pragma unroll 2
            for (int cc = 0; cc < 32; cc++) {
                int c = cbase + cc;
                float a0 = sa[c], a1 = sa[256+c], a2 = sa[512+c], a3 = sa[768+c];
                const float* row = &xs[c*129 + pg];
                #pragma unroll
                for (int j = 0; j < 4; j++) {
                    float v = row[32*j];
                    acc[0][j] += a0*v; acc[1][j] += a1*v;
                    acc[2][j] += a2*v; acc[3][j] += a3*v;
                    sx[j] += v; sxx[j] += v*v;
                }
            }
            #pragma unroll
            for (int j = 0; j < 4; j++) {
                sst[ch*256 +       pg + 32*j] = sx[j];
                sst[ch*256 + 128 + pg + 32*j] = sxx[j];
            }
        } else {
            #pragma unroll 2
            for (int cc = 0; cc < 32; cc++) {
                int c = cbase + cc;
                float a0 = sa[c], a1 = sa[256+c], a2 = sa[512+c], a3 = sa[768+c];
                const float* row = &xs[c*129 + pg];
                #pragma unroll
                for (int j = 0; j < 4; j++) {
                    float v = row[32*j];
                    acc[0][j] += a0*v; acc[1][j] += a1*v;
                    acc[2][j] += a2*v; acc[3][j] += a3*v;
                }
            }
        }
        #pragma unroll
        for (int k = 0; k < 4; k++)
            #pragma unroll
            for (int j = 0; j < 4; j++)
                sd[ch*512 + k*128 + pg + 32*j] = acc[k][j];
    }
    __syncthreads();

    // ---- softmax over K=4 per pixel, accumulate S/U ----
    if (tid < 128) {
        int p = tid;
        float d0=0,d1=0,d2=0,d3=0;
        #pragma unroll
        for (int h = 0; h < 8; h++) {
            d0 += sd[h*512 +       p];
            d1 += sd[h*512 + 128 + p];
            d2 += sd[h*512 + 256 + p];
            d3 += sd[h*512 + 384 + p];
        }
        float m, rs;
        if (first) {
            float a = 0.f, bb = 0.f;
            #pragma unroll
            for (int h = 0; h < 8; h++) { a += sst[h*256 + p]; bb += sst[h*256 + 128 + p]; }
            m = a * (1.0f/256.0f);
            float var = bb * (1.0f/256.0f) - m*m;
            rs = rsqrtf(var + 1e-5f);
            g_mean[b*NN + n0 + p] = m;
            g_rstd[b*NN + n0 + p] = rs;
        } else {
            m = smr[p]; rs = smr[128 + p];
        }
        float l0 = rs*(d0 - m*sc[0]) + sc[4];
        float l1 = rs*(d1 - m*sc[1]) + sc[5];
        float l2 = rs*(d2 - m*sc[2]) + sc[6];
        float l3 = rs*(d3 - m*sc[3]) + sc[7];
        float M = fmaxf(fmaxf(l0,l1), fmaxf(l2,l3));
        float e0 = __expf(l0-M), e1 = __expf(l1-M), e2 = __expf(l2-M), e3 = __expf(l3-M);
        float iz = 1.0f / (e0+e1+e2+e3);
        float at0 = e0*iz, at1 = e1*iz, at2 = e2*iz, at3 = e3*iz;
        tvv[p]       = at0*rs;
        tvv[128 + p] = at1*rs;
        tvv[256 + p] = at2*rs;
        tvv[384 + p] = at3*rs;
        float u0 = at0*rs*m, u1 = at1*rs*m, u2 = at2*rs*m, u3 = at3*rs*m;
        #pragma unroll
        for (int o = 16; o; o >>= 1) {
            at0 += __shfl_down_sync(0xffffffffu, at0, o);
            at1 += __shfl_down_sync(0xffffffffu, at1, o);
            at2 += __shfl_down_sync(0xffffffffu, at2, o);
            at3 += __shfl_down_sync(0xffffffffu, at3, o);
            u0  += __shfl_down_sync(0xffffffffu, u0,  o);
            u1  += __shfl_down_sync(0xffffffffu, u1,  o);
            u2  += __shfl_down_sync(0xffffffffu, u2,  o);
            u3  += __shfl_down_sync(0xffffffffu, u3,  o);
        }
        if ((tid & 31) == 0) {
            atomicAdd(&g_S[b*4+0], at0); atomicAdd(&g_S[b*4+1], at1);
            atomicAdd(&g_S[b*4+2], at2); atomicAdd(&g_S[b*4+3], at3);
            atomicAdd(&g_U[b*4+0], u0);  atomicAdd(&g_U[b*4+1], u1);
            atomicAdd(&g_U[b*4+2], u2);  atomicAdd(&g_U[b*4+3], u3);
        }
    }
    __syncthreads();

    // ---- phase 2: Araw[k,c] += sum_p t_k[p]*xs[c][p] ----
    {
        int cb = tid & 127, half = tid >> 7;
        float ac[4][2];
        #pragma unroll
        for (int k = 0; k < 4; k++) { ac[k][0] = 0.f; ac[k][1] = 0.f; }
        const float* r0 = &xs[cb*129];
        const float* r1 = &xs[(cb+128)*129];
        int ps = half * 64;
        #pragma unroll 4
        for (int pp = 0; pp < 64; pp++) {
            int p = ps + pp;
            float x0 = r0[p], x1 = r1[p];
            float t0 = tvv[p], t1 = tvv[128+p], t2 = tvv[256+p], t3 = tvv[384+p];
            ac[0][0] += t0*x0; ac[0][1] += t0*x1;
            ac[1][0] += t1*x0; ac[1][1] += t1*x1;
            ac[2][0] += t2*x0; ac[2][1] += t2*x1;
            ac[3][0] += t3*x0; ac[3][1] += t3*x1;
        }
        // partials into sd region: [half][k][c]
        #pragma unroll
        for (int k = 0; k < 4; k++) {
            sd[half*1024 + k*256 + cb]       = ac[k][0];
            sd[half*1024 + k*256 + cb + 128] = ac[k][1];
        }
    }
    __syncthreads();
    {
        int c = tid;
        #pragma unroll
        for (int k = 0; k < 4; k++)
            atomicAdd(&g_Araw[(b*4+k)*256 + c], sd[k*256 + c] + sd[1024 + k*256 + c]);
    }
}

// ---------------- slot update (per batch): updates, GRU-ish linear, MLP, (final head) --
__global__ void __launch_bounds__(256) k_update(
    const float* __restrict__ Wv, const float* __restrict__ bv,
    const float* __restrict__ Wu, const float* __restrict__ bu,
    const float* __restrict__ W1, const float* __restrict__ b1,
    const float* __restrict__ W2, const float* __restrict__ b2,
    const float* __restrict__ lig, const float* __restrict__ lib,
    const float* __restrict__ lmg, const float* __restrict__ lmb,
    const float* __restrict__ We1, const float* __restrict__ be1,
    const float* __restrict__ We2, const float* __restrict__ be2,
    int final, float* __restrict__ out, int out_size)
{
    __shared__ __align__(16) float prev[4][256];
    __shared__ __align__(16) float wx  [4][256];
    __shared__ __align__(16) float supd[4][256];
    __shared__ __align__(16) float s1  [4][256];
    __shared__ __align__(16) float mln [4][256];
    __shared__ __align__(16) float hbuf[4][512];
    __shared__ float red[16];
    __shared__ float ssumw[4];

    int b = blockIdx.x, tid = threadIdx.x;
    #pragma unroll
    for (int k = 0; k < 4; k++) prev[k][tid] = g_slots[(b*4+k)*256 + tid];

    float ligc = lig[tid], libc = lib[tid];
    #pragma unroll
    for (int k = 0; k < 4; k++) {
        float S = g_S[b*4+k], U = g_U[b*4+k];
        float inv = 1.0f / (S + 1e-8f);
        float A = ligc * (g_Araw[(b*4+k)*256 + tid] - U) + libc * S;
        wx[k][tid] = inv * A;
        if (tid == 0) ssumw[k] = S * inv;
    }
    __syncthreads();

    // updates[k][d] = wx[k] . Wv[d,:] + sumw_k * bv[d]
    {
        float bvd = bv[tid];
        float u0 = ssumw[0]*bvd, u1 = ssumw[1]*bvd, u2 = ssumw[2]*bvd, u3 = ssumw[3]*bvd;
        const float4* wv4 = (const float4*)(Wv + tid*256);
        const float4* w0 = (const float4*)wx[0];
        const float4* w1 = (const float4*)wx[1];
        const float4* w2 = (const float4*)wx[2];
        const float4* w3 = (const float4*)wx[3];
        #pragma unroll 8
        for (int i = 0; i < 64; i++) {
            float4 w = wv4[i];
            float4 a0 = w0[i], a1 = w1[i], a2 = w2[i], a3 = w3[i];
            u0 += w.x*a0.x + w.y*a0.y + w.z*a0.z + w.w*a0.w;
            u1 += w.x*a1.x + w.y*a1.y + w.z*a1.z + w.w*a1.w;
            u2 += w.x*a2.x + w.y*a2.y + w.z*a2.z + w.w*a2.w;
            u3 += w.x*a3.x + w.y*a3.y + w.z*a3.z + w.w*a3.w;
        }
        supd[0][tid]=u0; supd[1][tid]=u1; supd[2][tid]=u2; supd[3][tid]=u3;
    }
    __syncthreads();

    // slots1[k][d] = [prev|upd] . Wu[d,:] + bu[d] + prev[k][d]
    {
        float bud = bu[tid];
        float v0 = bud + prev[0][tid], v1 = bud + prev[1][tid];
        float v2 = bud + prev[2][tid], v3 = bud + prev[3][tid];
        const float4* wu4 = (const float4*)(Wu + tid*512);
        const float4* p0 = (const float4*)prev[0];
        const float4* p1 = (const float4*)prev[1];
        const float4* p2 = (const float4*)prev[2];
        const float4* p3 = (const float4*)prev[3];
        #pragma unroll 8
        for (int i = 0; i < 64; i++) {
            float4 w = wu4[i];
            float4 a0 = p0[i], a1 = p1[i], a2 = p2[i], a3 = p3[i];
            v0 += w.x*a0.x + w.y*a0.y + w.z*a0.z + w.w*a0.w;
            v1 += w.x*a1.x + w.y*a1.y + w.z*a1.z + w.w*a1.w;
            v2 += w.x*a2.x + w.y*a2.y + w.z*a2.z + w.w*a2.w;
            v3 += w.x*a3.x + w.y*a3.y + w.z*a3.z + w.w*a3.w;
        }
        const float4* q0 = (const float4*)supd[0];
        const float4* q1 = (const float4*)supd[1];
        const float4* q2 = (const float4*)supd[2];
        const float4* q3 = (const float4*)supd[3];
        #pragma unroll 8
        for (int i = 0; i < 64; i++) {
            float4 w = wu4[64 + i];
            float4 a0 = q0[i], a1 = q1[i], a2 = q2[i], a3 = q3[i];
            v0 += w.x*a0.x + w.y*a0.y + w.z*a0.z + w.w*a0.w;
            v1 += w.x*a1.x + w.y*a1.y + w.z*a1.z + w.w*a1.w;
            v2 += w.x*a2.x + w.y*a2.y + w.z*a2.z + w.w*a2.w;
            v3 += w.x*a3.x + w.y*a3.y + w.z*a3.z + w.w*a3.w;
        }
        s1[0][tid]=v0; s1[1][tid]=v1; s1[2][tid]=v2; s1[3][tid]=v3;
    }
    __syncthreads();

    // LN (ln_mlp) per slot
    float lmgc = lmg[tid], lmbc = lmb[tid];
    for (int k = 0; k < 4; k++) {
        float v = s1[k][tid];
        float a = v, bb = v*v;
        blockReduce2(a, bb, red);
        float m = a * (1.0f/256.0f);
        float var = bb * (1.0f/256.0f) - m*m;
        float rs = rsqrtf(var + 1e-5f);
        mln[k][tid] = (v - m) * rs * lmgc + lmbc;
    }
    __syncthreads();

    // h = gelu(mln @ W1^T + b1), exact erf gelu
    {
        const float4* m0 = (const float4*)mln[0];
        const float4* m1 = (const float4*)mln[1];
        const float4* m2 = (const float4*)mln[2];
        const float4* m3 = (const float4*)mln[3];
        #pragma unroll
        for (int rr = 0; rr < 2; rr++) {
            int hh = tid + rr*256;
            float bh = b1[hh];
            float h0 = bh, h1 = bh, h2 = bh, h3 = bh;
            const float4* w14 = (const float4*)(W1 + hh*256);
            #pragma unroll 8
            for (int i = 0; i < 64; i++) {
                float4 w = w14[i];
                float4 a0 = m0[i], a1 = m1[i], a2 = m2[i], a3 = m3[i];
                h0 += w.x*a0.x + w.y*a0.y + w.z*a0.z + w.w*a0.w;
                h1 += w.x*a1.x + w.y*a1.y + w.z*a1.z + w.w*a1.w;
                h2 += w.x*a2.x + w.y*a2.y + w.z*a2.z + w.w*a2.w;
                h3 += w.x*a3.x + w.y*a3.y + w.z*a3.z + w.w*a3.w;
            }
            hbuf[0][hh] = h0 * normcdff(h0);
            hbuf[1][hh] = h1 * normcdff(h1);
            hbuf[2][hh] = h2 * normcdff(h2);
            hbuf[3][hh] = h3 * normcdff(h3);
        }
    }
    __syncthreads();

    // slots = slots1 + h @ W2^T + b2
    {
        float b2d = b2[tid];
        float o0 = s1[0][tid] + b2d, o1 = s1[1][tid] + b2d;
        float o2 = s1[2][tid] + b2d, o3 = s1[3][tid] + b2d;
        const float4* w24 = (const float4*)(W2 + tid*512);
        const float4* h0 = (const float4*)hbuf[0];
        const float4* h1 = (const float4*)hbuf[1];
        const float4* h2 = (const float4*)hbuf[2];
        const float4* h3 = (const float4*)hbuf[3];
        #pragma unroll 8
        for (int i = 0; i < 128; i++) {
            float4 w = w24[i];
            float4 a0 = h0[i], a1 = h1[i], a2 = h2[i], a3 = h3[i];
            o0 += w.x*a0.x + w.y*a0.y + w.z*a0.z + w.w*a0.w;
            o1 += w.x*a1.x + w.y*a1.y + w.z*a1.z + w.w*a1.w;
            o2 += w.x*a2.x + w.y*a2.y + w.z*a2.z + w.w*a2.w;
            o3 += w.x*a3.x + w.y*a3.y + w.z*a3.z + w.w*a3.w;
        }
        g_slots[(b*4+0)*256 + tid] = o0;
        g_slots[(b*4+1)*256 + tid] = o1;
        g_slots[(b*4+2)*256 + tid] = o2;
        g_slots[(b*4+3)*256 + tid] = o3;
        if (final) { s1[0][tid]=o0; s1[1][tid]=o1; s1[2][tid]=o2; s1[3][tid]=o3; }
    }

    if (final) {
        __syncthreads();
        // e[k][j] = gelu(slots @ We1^T + be1), j < 128 ; reuse mln as e buffer
        if (tid < 128) {
            int j = tid;
            float bej = be1[j];
            float e0 = bej, e1 = bej, e2 = bej, e3 = bej;
            const float4* we4 = (const float4*)(We1 + j*256);
            const float4* t0 = (const float4*)s1[0];
            const float4* t1 = (const float4*)s1[1];
            const float4* t2 = (const float4*)s1[2];
            const float4* t3 = (const float4*)s1[3];
            #pragma unroll 8
            for (int i = 0; i < 64; i++) {
                float4 w = we4[i];
                float4 a0 = t0[i], a1 = t1[i], a2 = t2[i], a3 = t3[i];
                e0 += w.x*a0.x + w.y*a0.y + w.z*a0.z + w.w*a0.w;
                e1 += w.x*a1.x + w.y*a1.y + w.z*a1.z + w.w*a1.w;
                e2 += w.x*a2.x + w.y*a2.y + w.z*a2.z + w.w*a2.w;
                e3 += w.x*a3.x + w.y*a3.y + w.z*a3.z + w.w*a3.w;
            }
            mln[0][j] = e0 * normcdff(e0);
            mln[1][j] = e1 * normcdff(e1);
            mln[2][j] = e2 * normcdff(e2);
            mln[3][j] = e3 * normcdff(e3);
        }
        __syncthreads();
        if (tid < 128) {
            float w2j = We2[tid];
            float p0 = mln[0][tid]*w2j, p1 = mln[1][tid]*w2j;
            float p2 = mln[2][tid]*w2j, p3 = mln[3][tid]*w2j;
            #pragma unroll
            for (int o = 16; o; o >>= 1) {
                p0 += __shfl_down_sync(0xffffffffu, p0, o);
                p1 += __shfl_down_sync(0xffffffffu, p1, o);
                p2 += __shfl_down_sync(0xffffffffu, p2, o);
                p3 += __shfl_down_sync(0xffffffffu, p3, o);
            }
            if ((tid & 31) == 0) {
                int w = tid >> 5;
                red[w*4+0]=p0; red[w*4+1]=p1; red[w*4+2]=p2; red[w*4+3]=p3;
            }
        }
        __syncthreads();
        if (tid < 4 && out_size > BN*KN*CN) {
            float s = red[tid] + red[4+tid] + red[8+tid] + red[12+tid];
            float z = s + be2[0];
            out[BN*KN*CN + b*4 + tid] = 1.0f / (1.0f + __expf(-z));
        }
        #pragma unroll
        for (int k = 0; k < 4; k++)
            out[(b*4+k)*256 + tid] = s1[k][tid];
    }
}

// ---------------- launch ----------------
extern "C" void kernel_launch(void* const* d_in, const int* in_sizes, int n_in,
                              void* d_out, int out_size) {
    (void)in_sizes; (void)n_in;
    const float* x    = (const float*)d_in[0];
    const float* noise= (const float*)d_in[1];
    const float* mu   = (const float*)d_in[2];
    const float* lsig = (const float*)d_in[3];
    const float* lig  = (const float*)d_in[4];
    const float* lib  = (const float*)d_in[5];
    const float* lsg  = (const float*)d_in[6];
    const float* lsb  = (const float*)d_in[7];
    const float* lmg  = (const float*)d_in[8];
    const float* lmb  = (const float*)d_in[9];
    const float* Wq   = (const float*)d_in[10];
    const float* bq   = (const float*)d_in[11];
    const float* Wk   = (const float*)d_in[12];
    const float* bk   = (const float*)d_in[13];
    const float* Wv   = (const float*)d_in[14];
    const float* bv   = (const float*)d_in[15];
    const float* Wu   = (const float*)d_in[16];
    const float* bu   = (const float*)d_in[17];
    const float* W1   = (const float*)d_in[18];
    const float* b1   = (const float*)d_in[19];
    const float* W2   = (const float*)d_in[20];
    const float* b2   = (const float*)d_in[21];
    const float* We1  = (const float*)d_in[22];
    const float* be1  = (const float*)d_in[23];
    const float* We2  = (const float*)d_in[24];
    const float* be2  = (const float*)d_in[25];

    int smem = (256*129 + 1024 + 4096 + 2048 + 512 + 256 + 8) * 4;
    cudaFuncSetAttribute(k_attn, cudaFuncAttributeMaxDynamicSharedMemorySize, smem);

    k_init<<<BN*KN, CN>>>(noise, mu, lsig);
    for (int it = 0; it < 3; it++) {
        k_prep<<<BN*KN, CN>>>(Wq, bq, Wk, bk, lsg, lsb, lig, lib);
        dim3 g(32, 16);
        k_attn<<<g, 256, smem>>>(x, it == 0 ? 1 : 0);
        k_update<<<BN, CN>>>(Wv, bv, Wu, bu, W1, b1, W2, b2,
                             lig, lib, lmg, lmb, We1, be1, We2, be2,
                             it == 2 ? 1 : 0, (float*)d_out, out_size);
    }
}

// round 4
// speedup vs baseline: 1.4782x; 1.4782x over previous
#include <cuda_runtime.h>
#include <math.h>

#define BN 16
#define CN 256
#define NN 4096
#define KN 4
#define HN 512
#define SCALE 0.0625f   // 256^-0.5

// ---------------- scratch (device globals; no allocation) ----------------
__device__ float g_slots[BN*KN*CN];
__device__ float g_q    [BN*KN*CN];
__device__ float g_qkg  [BN*KN*CN];   // a[k][c] = scale*qk[c]*ln_in_g[c]
__device__ float g_G    [BN*KN];
__device__ float g_off  [BN*KN];
__device__ float g_S    [BN*KN];
__device__ float g_U    [BN*KN];
__device__ float g_Araw [BN*KN*CN];
__device__ float g_mean [BN*NN];
__device__ float g_rstd [BN*NN];
__device__ float g_upd  [BN*KN*CN];
__device__ float g_s1   [BN*KN*CN];
__device__ float g_h    [BN*KN*HN];
__device__ float g_z    [BN*KN];

// 256-thread dual block reduction; red >= 16 floats.
__device__ __forceinline__ void blockReduce2(float& a, float& b, float* red) {
    #pragma unroll
    for (int o = 16; o; o >>= 1) {
        a += __shfl_down_sync(0xffffffffu, a, o);
        b += __shfl_down_sync(0xffffffffu, b, o);
    }
    int w = threadIdx.x >> 5;
    if ((threadIdx.x & 31) == 0) { red[w] = a; red[8 + w] = b; }
    __syncthreads();
    a = red[0]+red[1]+red[2]+red[3]+red[4]+red[5]+red[6]+red[7];
    b = red[8]+red[9]+red[10]+red[11]+red[12]+red[13]+red[14]+red[15];
    __syncthreads();
}

// ---------------- init ----------------
__global__ void k_init(const float* __restrict__ noise, const float* __restrict__ mu,
                       const float* __restrict__ lsig) {
    int r = blockIdx.x, c = threadIdx.x;
    g_slots[r*CN + c] = mu[c] + expf(lsig[c]) * noise[r*CN + c];
    g_Araw[r*CN + c] = 0.f;
    if (c == 0) { g_S[r]=0.f; g_U[r]=0.f; g_G[r]=0.f; g_off[r]=0.f; g_z[r]=0.f; }
}

// ---------------- q = LN(slots)@Wq^T + bq   (chunked over output dims) ----------
// grid (16 batches, 4 chunks of 64 dims), 256 threads
__global__ void __launch_bounds__(256) k_q(
    const float* __restrict__ Wq, const float* __restrict__ bq,
    const float* __restrict__ bk,
    const float* __restrict__ lsg, const float* __restrict__ lsb)
{
    __shared__ __align__(16) float sv[4][256];
    __shared__ float red[16];
    int b = blockIdx.x, ch = blockIdx.y, tid = threadIdx.x;
    float lg = lsg[tid], lb = lsb[tid];
    #pragma unroll
    for (int k = 0; k < 4; k++) {
        float v = g_slots[(b*4+k)*CN + tid];
        float a = v, bb = v*v;
        blockReduce2(a, bb, red);
        float m = a * (1.0f/CN);
        float var = bb * (1.0f/CN) - m*m;
        float rs = rsqrtf(var + 1e-5f);
        sv[k][tid] = (v - m) * rs * lg + lb;
    }
    __syncthreads();

    int warp = tid >> 5, lane = tid & 31;
    float qb[4] = {0,0,0,0};
    #pragma unroll
    for (int j = 0; j < 8; j++) {
        int dd = ch*64 + warp*8 + j;
        const float4* w = (const float4*)(Wq + dd*CN + lane*8);
        float4 w0 = w[0], w1 = w[1];
        float acc[4];
        #pragma unroll
        for (int k = 0; k < 4; k++) {
            const float4* sk = (const float4*)&sv[k][lane*8];
            float4 a0 = sk[0], a1 = sk[1];
            acc[k] = w0.x*a0.x + w0.y*a0.y + w0.z*a0.z + w0.w*a0.w
                   + w1.x*a1.x + w1.y*a1.y + w1.z*a1.z + w1.w*a1.w;
        }
        #pragma unroll
        for (int o = 16; o; o >>= 1)
            #pragma unroll
            for (int k = 0; k < 4; k++)
                acc[k] += __shfl_down_sync(0xffffffffu, acc[k], o);
        if (lane == 0) {
            float bqd = bq[dd], bkd = bk[dd];
            #pragma unroll
            for (int k = 0; k < 4; k++) {
                float q = acc[k] + bqd;
                g_q[(b*4+k)*CN + dd] = q;
                qb[k] += q * bkd;
            }
        }
    }
    if (lane == 0) {
        #pragma unroll
        for (int k = 0; k < 4; k++) atomicAdd(&g_off[b*4+k], SCALE * qb[k]);
    }
}

// ---------------- a = scale*(q@Wk)*lig ; G, off partials  ------------------
// grid (16, 4 chunks of 64 cols), 256 threads (4 slots x 64 cols)
__global__ void __launch_bounds__(256) k_a(
    const float* __restrict__ Wk,
    const float* __restrict__ lig, const float* __restrict__ lib)
{
    __shared__ __align__(16) float sq[4][256];
    int b = blockIdx.x, ch = blockIdx.y, tid = threadIdx.x;
    #pragma unroll
    for (int k = 0; k < 4; k++) sq[k][tid] = g_q[(b*4+k)*CN + tid];
    __syncthreads();

    int slot = tid >> 6, cl = tid & 63, c = ch*64 + cl;
    float acc = 0.f;
    #pragma unroll 8
    for (int d = 0; d < CN; d++) acc += sq[slot][d] * Wk[d*CN + c];
    float qk = SCALE * acc;
    float av = qk * lig[c];
    g_qkg[(b*4+slot)*CN + c] = av;
    float offp = qk * lib[c];
    float Gs = av;
    #pragma unroll
    for (int o = 16; o; o >>= 1) {
        Gs   += __shfl_down_sync(0xffffffffu, Gs,   o);
        offp += __shfl_down_sync(0xffffffffu, offp, o);
    }
    if ((tid & 31) == 0) {
        atomicAdd(&g_G[b*4+slot], Gs);
        atomicAdd(&g_off[b*4+slot], offp);
    }
}

// ---------------- main attention pass (unchanged) ----------------
__global__ void __launch_bounds__(256) k_attn(const float* __restrict__ x, int first) {
    extern __shared__ float sm[];
    float* xs  = sm;               // [256][129]
    float* sa  = xs  + 256*129;    // [4][256]
    float* sd  = sa  + 1024;       // [8][4][128] ; reused [2][4][256]
    float* sst = sd  + 4096;       // [8][2][128]
    float* tvv = sst + 2048;       // [4][128]
    float* smr = tvv + 512;        // [2][128]
    float* sc  = smr + 256;        // G[4], off[4]

    int b = blockIdx.y, t = blockIdx.x, tid = threadIdx.x;
    int n0 = t * 128;

    for (int i = tid; i < 1024; i += 256) sa[i] = g_qkg[b*1024 + i];
    if (tid < 4) { sc[tid] = g_G[b*4 + tid]; sc[4+tid] = g_off[b*4 + tid]; }
    if (!first && tid < 128) {
        smr[tid]       = g_mean[b*NN + n0 + tid];
        smr[128 + tid] = g_rstd[b*NN + n0 + tid];
    }
    const float* xb = x + (size_t)b*CN*NN + n0;
    for (int i = tid; i < 256*128; i += 256) {
        int c = i >> 7, p = i & 127;
        xs[c*129 + p] = xb[c*4096 + p];
    }
    __syncthreads();

    {
        int pg = tid & 31, ch = tid >> 5;
        float acc[4][4];
        #pragma unroll
        for (int k = 0; k < 4; k++)
            #pragma unroll
            for (int j = 0; j < 4; j++) acc[k][j] = 0.f;

        int cbase = ch * 32;
        if (first) {
            float sx[4] = {0,0,0,0}, sxx[4] = {0,0,0,0};
            #pragma unroll 2
            for (int cc = 0; cc < 32; cc++) {
                int c = cbase + cc;
                float a0 = sa[c], a1 = sa[256+c], a2 = sa[512+c], a3 = sa[768+c];
                const float* row = &xs[c*129 + pg];
                #pragma unroll
                for (int j = 0; j < 4; j++) {
                    float v = row[32*j];
                    acc[0][j] += a0*v; acc[1][j] += a1*v;
                    acc[2][j] += a2*v; acc[3][j] += a3*v;
                    sx[j] += v; sxx[j] += v*v;
                }
            }
            #pragma unroll
            for (int j = 0; j < 4; j++) {
                sst[ch*256 +       pg + 32*j] = sx[j];
                sst[ch*256 + 128 + pg + 32*j] = sxx[j];
            }
        } else {
            #pragma unroll 2
            for (int cc = 0; cc < 32; cc++) {
                int c = cbase + cc;
                float a0 = sa[c], a1 = sa[256+c], a2 = sa[512+c], a3 = sa[768+c];
                const float* row = &xs[c*129 + pg];
                #pragma unroll
                for (int j = 0; j < 4; j++) {
                    float v = row[32*j];
                    acc[0][j] += a0*v; acc[1][j] += a1*v;
                    acc[2][j] += a2*v; acc[3][j] += a3*v;
                }
            }
        }
        #pragma unroll
        for (int k = 0; k < 4; k++)
            #pragma unroll
            for (int j = 0; j < 4; j++)
                sd[ch*512 + k*128 + pg + 32*j] = acc[k][j];
    }
    __syncthreads();

    if (tid < 128) {
        int p = tid;
        float d0=0,d1=0,d2=0,d3=0;
        #pragma unroll
        for (int h = 0; h < 8; h++) {
            d0 += sd[h*512 +       p];
            d1 += sd[h*512 + 128 + p];
            d2 += sd[h*512 + 256 + p];
            d3 += sd[h*512 + 384 + p];
        }
        float m, rs;
        if (first) {
            float a = 0.f, bb = 0.f;
            #pragma unroll
            for (int h = 0; h < 8; h++) { a += sst[h*256 + p]; bb += sst[h*256 + 128 + p]; }
            m = a * (1.0f/256.0f);
            float var = bb * (1.0f/256.0f) - m*m;
            rs = rsqrtf(var + 1e-5f);
            g_mean[b*NN + n0 + p] = m;
            g_rstd[b*NN + n0 + p] = rs;
        } else {
            m = smr[p]; rs = smr[128 + p];
        }
        float l0 = rs*(d0 - m*sc[0]) + sc[4];
        float l1 = rs*(d1 - m*sc[1]) + sc[5];
        float l2 = rs*(d2 - m*sc[2]) + sc[6];
        float l3 = rs*(d3 - m*sc[3]) + sc[7];
        float M = fmaxf(fmaxf(l0,l1), fmaxf(l2,l3));
        float e0 = __expf(l0-M), e1 = __expf(l1-M), e2 = __expf(l2-M), e3 = __expf(l3-M);
        float iz = 1.0f / (e0+e1+e2+e3);
        float at0 = e0*iz, at1 = e1*iz, at2 = e2*iz, at3 = e3*iz;
        tvv[p]       = at0*rs;
        tvv[128 + p] = at1*rs;
        tvv[256 + p] = at2*rs;
        tvv[384 + p] = at3*rs;
        float u0 = at0*rs*m, u1 = at1*rs*m, u2 = at2*rs*m, u3 = at3*rs*m;
        #pragma unroll
        for (int o = 16; o; o >>= 1) {
            at0 += __shfl_down_sync(0xffffffffu, at0, o);
            at1 += __shfl_down_sync(0xffffffffu, at1, o);
            at2 += __shfl_down_sync(0xffffffffu, at2, o);
            at3 += __shfl_down_sync(0xffffffffu, at3, o);
            u0  += __shfl_down_sync(0xffffffffu, u0,  o);
            u1  += __shfl_down_sync(0xffffffffu, u1,  o);
            u2  += __shfl_down_sync(0xffffffffu, u2,  o);
            u3  += __shfl_down_sync(0xffffffffu, u3,  o);
        }
        if ((tid & 31) == 0) {
            atomicAdd(&g_S[b*4+0], at0); atomicAdd(&g_S[b*4+1], at1);
            atomicAdd(&g_S[b*4+2], at2); atomicAdd(&g_S[b*4+3], at3);
            atomicAdd(&g_U[b*4+0], u0);  atomicAdd(&g_U[b*4+1], u1);
            atomicAdd(&g_U[b*4+2], u2);  atomicAdd(&g_U[b*4+3], u3);
        }
    }
    __syncthreads();

    {
        int cb = tid & 127, half = tid >> 7;
        float ac[4][2];
        #pragma unroll
        for (int k = 0; k < 4; k++) { ac[k][0] = 0.f; ac[k][1] = 0.f; }
        const float* r0 = &xs[cb*129];
        const float* r1 = &xs[(cb+128)*129];
        int ps = half * 64;
        #pragma unroll 4
        for (int pp = 0; pp < 64; pp++) {
            int p = ps + pp;
            float x0 = r0[p], x1 = r1[p];
            float t0 = tvv[p], t1 = tvv[128+p], t2 = tvv[256+p], t3 = tvv[384+p];
            ac[0][0] += t0*x0; ac[0][1] += t0*x1;
            ac[1][0] += t1*x0; ac[1][1] += t1*x1;
            ac[2][0] += t2*x0; ac[2][1] += t2*x1;
            ac[3][0] += t3*x0; ac[3][1] += t3*x1;
        }
        #pragma unroll
        for (int k = 0; k < 4; k++) {
            sd[half*1024 + k*256 + cb]       = ac[k][0];
            sd[half*1024 + k*256 + cb + 128] = ac[k][1];
        }
    }
    __syncthreads();
    {
        int c = tid;
        #pragma unroll
        for (int k = 0; k < 4; k++)
            atomicAdd(&g_Araw[(b*4+k)*256 + c], sd[k*256 + c] + sd[1024 + k*256 + c]);
    }
}

// ---------------- updates = wx@Wv^T + sumw*bv  (chunked) -------------------
// grid (16, 4 chunks of 64 dims)
__global__ void __launch_bounds__(256) k_uv(
    const float* __restrict__ Wv, const float* __restrict__ bv,
    const float* __restrict__ lig, const float* __restrict__ lib)
{
    __shared__ __align__(16) float wx[4][256];
    __shared__ float sumw[4];
    int b = blockIdx.x, ch = blockIdx.y, tid = threadIdx.x;
    if (tid < 4) { float S = g_S[b*4+tid]; sumw[tid] = S / (S + 1e-8f); }
    float ligc = lig[tid], libc = lib[tid];
    #pragma unroll
    for (int k = 0; k < 4; k++) {
        float S = g_S[b*4+k], U = g_U[b*4+k];
        wx[k][tid] = (ligc*(g_Araw[(b*4+k)*CN + tid] - U) + libc*S) / (S + 1e-8f);
    }
    __syncthreads();

    int warp = tid >> 5, lane = tid & 31;
    #pragma unroll
    for (int j = 0; j < 8; j++) {
        int dd = ch*64 + warp*8 + j;
        const float4* w = (const float4*)(Wv + dd*CN + lane*8);
        float4 w0 = w[0], w1 = w[1];
        float acc[4];
        #pragma unroll
        for (int k = 0; k < 4; k++) {
            const float4* sk = (const float4*)&wx[k][lane*8];
            float4 a0 = sk[0], a1 = sk[1];
            acc[k] = w0.x*a0.x + w0.y*a0.y + w0.z*a0.z + w0.w*a0.w
                   + w1.x*a1.x + w1.y*a1.y + w1.z*a1.z + w1.w*a1.w;
        }
        #pragma unroll
        for (int o = 16; o; o >>= 1)
            #pragma unroll
            for (int k = 0; k < 4; k++)
                acc[k] += __shfl_down_sync(0xffffffffu, acc[k], o);
        if (lane == 0) {
            float bvd = bv[dd];
            #pragma unroll
            for (int k = 0; k < 4; k++)
                g_upd[(b*4+k)*CN + dd] = acc[k] + sumw[k]*bvd;
        }
    }
}

// ---------------- s1 = [prev|upd]@Wu^T + bu + prev  (chunked) ---------------
// grid (16, 4 chunks of 64 dims)
__global__ void __launch_bounds__(256) k_uu(
    const float* __restrict__ Wu, const float* __restrict__ bu)
{
    __shared__ __align__(16) float cat[4][512];
    int b = blockIdx.x, ch = blockIdx.y, tid = threadIdx.x;
    #pragma unroll
    for (int k = 0; k < 4; k++) {
        cat[k][tid]       = g_slots[(b*4+k)*CN + tid];
        cat[k][256 + tid] = g_upd  [(b*4+k)*CN + tid];
    }
    __syncthreads();

    int warp = tid >> 5, lane = tid & 31;
    #pragma unroll
    for (int j = 0; j < 8; j++) {
        int dd = ch*64 + warp*8 + j;
        const float4* w = (const float4*)(Wu + dd*512 + lane*16);
        float4 w0 = w[0], w1 = w[1], w2 = w[2], w3 = w[3];
        float acc[4];
        #pragma unroll
        for (int k = 0; k < 4; k++) {
            const float4* sk = (const float4*)&cat[k][lane*16];
            float4 a0 = sk[0], a1 = sk[1], a2 = sk[2], a3 = sk[3];
            acc[k] = w0.x*a0.x + w0.y*a0.y + w0.z*a0.z + w0.w*a0.w
                   + w1.x*a1.x + w1.y*a1.y + w1.z*a1.z + w1.w*a1.w
                   + w2.x*a2.x + w2.y*a2.y + w2.z*a2.z + w2.w*a2.w
                   + w3.x*a3.x + w3.y*a3.y + w3.z*a3.z + w3.w*a3.w;
        }
        #pragma unroll
        for (int o = 16; o; o >>= 1)
            #pragma unroll
            for (int k = 0; k < 4; k++)
                acc[k] += __shfl_down_sync(0xffffffffu, acc[k], o);
        if (lane == 0) {
            float bud = bu[dd];
            #pragma unroll
            for (int k = 0; k < 4; k++)
                g_s1[(b*4+k)*CN + dd] = acc[k] + bud + cat[k][dd];
        }
    }
}

// ---------------- h = gelu(LN(s1)@W1^T + b1)  (chunked) ---------------------
// grid (16, 8 chunks of 64 dims)
__global__ void __launch_bounds__(256) k_h(
    const float* __restrict__ W1, const float* __restrict__ b1,
    const float* __restrict__ lmg, const float* __restrict__ lmb)
{
    __shared__ __align__(16) float mln[4][256];
    __shared__ float red[16];
    int b = blockIdx.x, ch = blockIdx.y, tid = threadIdx.x;
    float lg = lmg[tid], lb = lmb[tid];
    #pragma unroll
    for (int k = 0; k < 4; k++) {
        float v = g_s1[(b*4+k)*CN + tid];
        float a = v, bb = v*v;
        blockReduce2(a, bb, red);
        float m = a * (1.0f/CN);
        float var = bb * (1.0f/CN) - m*m;
        float rs = rsqrtf(var + 1e-5f);
        mln[k][tid] = (v - m) * rs * lg + lb;
    }
    __syncthreads();

    int warp = tid >> 5, lane = tid & 31;
    #pragma unroll
    for (int j = 0; j < 8; j++) {
        int dd = ch*64 + warp*8 + j;
        const float4* w = (const float4*)(W1 + dd*CN + lane*8);
        float4 w0 = w[0], w1 = w[1];
        float acc[4];
        #pragma unroll
        for (int k = 0; k < 4; k++) {
            const float4* sk = (const float4*)&mln[k][lane*8];
            float4 a0 = sk[0], a1 = sk[1];
            acc[k] = w0.x*a0.x + w0.y*a0.y + w0.z*a0.z + w0.w*a0.w
                   + w1.x*a1.x + w1.y*a1.y + w1.z*a1.z + w1.w*a1.w;
        }
        #pragma unroll
        for (int o = 16; o; o >>= 1)
            #pragma unroll
            for (int k = 0; k < 4; k++)
                acc[k] += __shfl_down_sync(0xffffffffu, acc[k], o);
        if (lane == 0) {
            float bh = b1[dd];
            #pragma unroll
            for (int k = 0; k < 4; k++) {
                float h = acc[k] + bh;
                g_h[(b*4+k)*HN + dd] = h * normcdff(h);
            }
        }
    }
}

// ---------------- slots = s1 + h@W2^T + b2  (chunked); zero next accums -----
// grid (16, 4 chunks of 64 dims)
__global__ void __launch_bounds__(256) k_o(
    const float* __restrict__ W2, const float* __restrict__ b2,
    int final, float* __restrict__ out)
{
    __shared__ __align__(16) float hsm[4][512];
    int b = blockIdx.x, ch = blockIdx.y, tid = threadIdx.x;
    #pragma unroll
    for (int k = 0; k < 4; k++) {
        hsm[k][tid]       = g_h[(b*4+k)*HN + tid];
        hsm[k][256 + tid] = g_h[(b*4+k)*HN + 256 + tid];
    }
    __syncthreads();

    int warp = tid >> 5, lane = tid & 31;
    #pragma unroll
    for (int j = 0; j < 8; j++) {
        int dd = ch*64 + warp*8 + j;
        const float4* w = (const float4*)(W2 + dd*512 + lane*16);
        float4 w0 = w[0], w1 = w[1], w2 = w[2], w3 = w[3];
        float acc[4];
        #pragma unroll
        for (int k = 0; k < 4; k++) {
            const float4* sk = (const float4*)&hsm[k][lane*16];
            float4 a0 = sk[0], a1 = sk[1], a2 = sk[2], a3 = sk[3];
            acc[k] = w0.x*a0.x + w0.y*a0.y + w0.z*a0.z + w0.w*a0.w
                   + w1.x*a1.x + w1.y*a1.y + w1.z*a1.z + w1.w*a1.w
                   + w2.x*a2.x + w2.y*a2.y + w2.z*a2.z + w2.w*a2.w
                   + w3.x*a3.x + w3.y*a3.y + w3.z*a3.z + w3.w*a3.w;
        }
        #pragma unroll
        for (int o = 16; o; o >>= 1)
            #pragma unroll
            for (int k = 0; k < 4; k++)
                acc[k] += __shfl_down_sync(0xffffffffu, acc[k], o);
        if (lane == 0) {
            float b2d = b2[dd];
            #pragma unroll
            for (int k = 0; k < 4; k++) {
                float o_ = acc[k] + b2d + g_s1[(b*4+k)*CN + dd];
                g_slots[(b*4+k)*CN + dd] = o_;
                if (final) out[(b*4+k)*CN + dd] = o_;
            }
        }
    }

    // zero accumulators for next iteration (consumers of this iter already ran)
    int kk = tid >> 6, cl = tid & 63;
    g_Araw[(b*4+kk)*CN + ch*64 + cl] = 0.f;
    if (ch == 0 && tid < 4) {
        g_S[b*4+tid] = 0.f; g_U[b*4+tid] = 0.f;
        g_G[b*4+tid] = 0.f; g_off[b*4+tid] = 0.f;
    }
}

// ---------------- final head: z partials ----------------
// grid (16, 2 chunks of 64 e-dims)
__global__ void __launch_bounds__(256) k_f1(
    const float* __restrict__ We1, const float* __restrict__ be1,
    const float* __restrict__ We2)
{
    __shared__ __align__(16) float sl[4][256];
    int b = blockIdx.x, ch = blockIdx.y, tid = threadIdx.x;
    #pragma unroll
    for (int k = 0; k < 4; k++) sl[k][tid] = g_slots[(b*4+k)*CN + tid];
    __syncthreads();

    int warp = tid >> 5, lane = tid & 31;
    float zp[4] = {0,0,0,0};
    #pragma unroll
    for (int j = 0; j < 8; j++) {
        int dd = ch*64 + warp*8 + j;   // dd < 128
        const float4* w = (const float4*)(We1 + dd*CN + lane*8);
        float4 w0 = w[0], w1 = w[1];
        float acc[4];
        #pragma unroll
        for (int k = 0; k < 4; k++) {
            const float4* sk = (const float4*)&sl[k][lane*8];
            float4 a0 = sk[0], a1 = sk[1];
            acc[k] = w0.x*a0.x + w0.y*a0.y + w0.z*a0.z + w0.w*a0.w
                   + w1.x*a1.x + w1.y*a1.y + w1.z*a1.z + w1.w*a1.w;
        }
        #pragma unroll
        for (int o = 16; o; o >>= 1)
            #pragma unroll
            for (int k = 0; k < 4; k++)
                acc[k] += __shfl_down_sync(0xffffffffu, acc[k], o);
        if (lane == 0) {
            float bed = be1[dd], wed = We2[dd];
            #pragma unroll
            for (int k = 0; k < 4; k++) {
                float e = acc[k] + bed;
                zp[k] += (e * normcdff(e)) * wed;
            }
        }
    }
    if (lane == 0) {
        #pragma unroll
        for (int k = 0; k < 4; k++) atomicAdd(&g_z[b*4+k], zp[k]);
    }
}

__global__ void k_f2(const float* __restrict__ be2, float* __restrict__ out, int out_size) {
    int r = threadIdx.x;
    if (out_size > BN*KN*CN) {
        float z = g_z[r] + be2[0];
        out[BN*KN*CN + r] = 1.0f / (1.0f + __expf(-z));
    }
}

// ---------------- launch ----------------
extern "C" void kernel_launch(void* const* d_in, const int* in_sizes, int n_in,
                              void* d_out, int out_size) {
    (void)in_sizes; (void)n_in;
    const float* x    = (const float*)d_in[0];
    const float* noise= (const float*)d_in[1];
    const float* mu   = (const float*)d_in[2];
    const float* lsig = (const float*)d_in[3];
    const float* lig  = (const float*)d_in[4];
    const float* lib  = (const float*)d_in[5];
    const float* lsg  = (const float*)d_in[6];
    const float* lsb  = (const float*)d_in[7];
    const float* lmg  = (const float*)d_in[8];
    const float* lmb  = (const float*)d_in[9];
    const float* Wq   = (const float*)d_in[10];
    const float* bq   = (const float*)d_in[11];
    const float* Wk   = (const float*)d_in[12];
    const float* bk   = (const float*)d_in[13];
    const float* Wv   = (const float*)d_in[14];
    const float* bv   = (const float*)d_in[15];
    const float* Wu   = (const float*)d_in[16];
    const float* bu   = (const float*)d_in[17];
    const float* W1   = (const float*)d_in[18];
    const float* b1   = (const float*)d_in[19];
    const float* W2   = (const float*)d_in[20];
    const float* b2   = (const float*)d_in[21];
    const float* We1  = (const float*)d_in[22];
    const float* be1  = (const float*)d_in[23];
    const float* We2  = (const float*)d_in[24];
    const float* be2  = (const float*)d_in[25];

    int smem = (256*129 + 1024 + 4096 + 2048 + 512 + 256 + 8) * 4;
    cudaFuncSetAttribute(k_attn, cudaFuncAttributeMaxDynamicSharedMemorySize, smem);

    k_init<<<BN*KN, CN>>>(noise, mu, lsig);
    for (int it = 0; it < 3; it++) {
        k_q<<<dim3(16,4), 256>>>(Wq, bq, bk, lsg, lsb);
        k_a<<<dim3(16,4), 256>>>(Wk, lig, lib);
        k_attn<<<dim3(32,16), 256, smem>>>(x, it == 0 ? 1 : 0);
        k_uv<<<dim3(16,4), 256>>>(Wv, bv, lig, lib);
        k_uu<<<dim3(16,4), 256>>>(Wu, bu);
        k_h <<<dim3(16,8), 256>>>(W1, b1, lmg, lmb);
        k_o <<<dim3(16,4), 256>>>(W2, b2, it == 2 ? 1 : 0, (float*)d_out);
    }
    k_f1<<<dim3(16,2), 256>>>(We1, be1, We2);
    k_f2<<<1, 64>>>(be2, (float*)d_out, out_size);
}

// round 6
// speedup vs baseline: 1.8780x; 1.2704x over previous
#include <cuda_runtime.h>
#include <math.h>

#define BN 16
#define CN 256
#define NN 4096
#define KN 4
#define HN 512
#define SCALE 0.0625f   // 256^-0.5

// ---------------- scratch (device globals; no allocation) ----------------
__device__ float g_slots[BN*KN*CN];
__device__ float g_q    [BN*KN*CN];
__device__ float g_qkg  [BN*KN*CN];   // a[k][c] = scale*qk[c]*ln_in_g[c]
__device__ float g_G    [BN*KN];
__device__ float g_off  [BN*KN];
__device__ float g_S    [BN*KN];
__device__ float g_U    [BN*KN];
__device__ float g_Araw [BN*KN*CN];
__device__ float g_mean [BN*NN];
__device__ float g_rstd [BN*NN];
__device__ float g_upd  [BN*KN*CN];
__device__ float g_s1   [BN*KN*CN];
__device__ float g_h    [BN*KN*HN];
__device__ float g_z    [BN*KN];

// 256-thread dual block reduction; red >= 16 floats.
__device__ __forceinline__ void blockReduce2(float& a, float& b, float* red) {
    #pragma unroll
    for (int o = 16; o; o >>= 1) {
        a += __shfl_down_sync(0xffffffffu, a, o);
        b += __shfl_down_sync(0xffffffffu, b, o);
    }
    int w = threadIdx.x >> 5;
    if ((threadIdx.x & 31) == 0) { red[w] = a; red[8 + w] = b; }
    __syncthreads();
    a = red[0]+red[1]+red[2]+red[3]+red[4]+red[5]+red[6]+red[7];
    b = red[8]+red[9]+red[10]+red[11]+red[12]+red[13]+red[14]+red[15];
    __syncthreads();
}

// ---------------- init ----------------
__global__ void k_init(const float* __restrict__ noise, const float* __restrict__ mu,
                       const float* __restrict__ lsig) {
    int r = blockIdx.x, c = threadIdx.x;
    g_slots[r*CN + c] = mu[c] + expf(lsig[c]) * noise[r*CN + c];
    g_Araw[r*CN + c] = 0.f;
    if (c == 0) { g_S[r]=0.f; g_U[r]=0.f; g_G[r]=0.f; g_off[r]=0.f; g_z[r]=0.f; }
}

// ---------------- q = LN(slots)@Wq^T + bq   (chunked over output dims) ----------
__global__ void __launch_bounds__(256) k_q(
    const float* __restrict__ Wq, const float* __restrict__ bq,
    const float* __restrict__ bk,
    const float* __restrict__ lsg, const float* __restrict__ lsb)
{
    __shared__ __align__(16) float sv[4][256];
    __shared__ float red[16];
    int b = blockIdx.x, ch = blockIdx.y, tid = threadIdx.x;
    float lg = lsg[tid], lb = lsb[tid];
    #pragma unroll
    for (int k = 0; k < 4; k++) {
        float v = g_slots[(b*4+k)*CN + tid];
        float a = v, bb = v*v;
        blockReduce2(a, bb, red);
        float m = a * (1.0f/CN);
        float var = bb * (1.0f/CN) - m*m;
        float rs = rsqrtf(var + 1e-5f);
        sv[k][tid] = (v - m) * rs * lg + lb;
    }
    __syncthreads();

    int warp = tid >> 5, lane = tid & 31;
    float qb[4] = {0,0,0,0};
    #pragma unroll
    for (int j = 0; j < 8; j++) {
        int dd = ch*64 + warp*8 + j;
        const float4* w = (const float4*)(Wq + dd*CN + lane*8);
        float4 w0 = w[0], w1 = w[1];
        float acc[4];
        #pragma unroll
        for (int k = 0; k < 4; k++) {
            const float4* sk = (const float4*)&sv[k][lane*8];
            float4 a0 = sk[0], a1 = sk[1];
            acc[k] = w0.x*a0.x + w0.y*a0.y + w0.z*a0.z + w0.w*a0.w
                   + w1.x*a1.x + w1.y*a1.y + w1.z*a1.z + w1.w*a1.w;
        }
        #pragma unroll
        for (int o = 16; o; o >>= 1)
            #pragma unroll
            for (int k = 0; k < 4; k++)
                acc[k] += __shfl_down_sync(0xffffffffu, acc[k], o);
        if (lane == 0) {
            float bqd = bq[dd], bkd = bk[dd];
            #pragma unroll
            for (int k = 0; k < 4; k++) {
                float q = acc[k] + bqd;
                g_q[(b*4+k)*CN + dd] = q;
                qb[k] += q * bkd;
            }
        }
    }
    if (lane == 0) {
        #pragma unroll
        for (int k = 0; k < 4; k++) atomicAdd(&g_off[b*4+k], SCALE * qb[k]);
    }
}

// ---------------- a = scale*(q@Wk)*lig ; G, off partials  ------------------
__global__ void __launch_bounds__(256) k_a(
    const float* __restrict__ Wk,
    const float* __restrict__ lig, const float* __restrict__ lib)
{
    __shared__ __align__(16) float sq[4][256];
    int b = blockIdx.x, ch = blockIdx.y, tid = threadIdx.x;
    #pragma unroll
    for (int k = 0; k < 4; k++) sq[k][tid] = g_q[(b*4+k)*CN + tid];
    __syncthreads();

    int slot = tid >> 6, cl = tid & 63, c = ch*64 + cl;
    float acc = 0.f;
    #pragma unroll 8
    for (int d = 0; d < CN; d++) acc += sq[slot][d] * Wk[d*CN + c];
    float qk = SCALE * acc;
    float av = qk * lig[c];
    g_qkg[(b*4+slot)*CN + c] = av;
    float offp = qk * lib[c];
    float Gs = av;
    #pragma unroll
    for (int o = 16; o; o >>= 1) {
        Gs   += __shfl_down_sync(0xffffffffu, Gs,   o);
        offp += __shfl_down_sync(0xffffffffu, offp, o);
    }
    if ((tid & 31) == 0) {
        atomicAdd(&g_G[b*4+slot], Gs);
        atomicAdd(&g_off[b*4+slot], offp);
    }
}

// ---------------- main attention pass (rewritten: no x staging) ----------------
// grid (16 batches, 8 pixel-tiles of 512), 256 threads.
__global__ void __launch_bounds__(256) k_attn(const float* __restrict__ x, int first) {
    __shared__ __align__(16) float sa[1024];    // [c][k]: folded a, float4 per channel
    __shared__ __align__(16) float st[4][512];  // t_k = attn*rs per pixel
    __shared__ float sc[8];                     // G[4], off[4]

    int b = blockIdx.x, t = blockIdx.y, tid = threadIdx.x;
    int n0 = t * 512;

    for (int i = tid; i < 1024; i += 256) {
        int k = i >> 8, c = i & 255;
        sa[c*4 + k] = g_qkg[b*1024 + i];
    }
    if (tid < 4) { sc[tid] = g_G[b*4 + tid]; sc[4+tid] = g_off[b*4 + tid]; }
    __syncthreads();

    // ---- phase 1: per-pixel dots over channels (2 pixels/thread, float2) ----
    const float* xb = x + (size_t)b*CN*NN + n0 + 2*tid;
    float d00=0,d01=0,d10=0,d11=0,d20=0,d21=0,d30=0,d31=0;
    float sx0=0,sx1=0,ss0=0,ss1=0;
    if (first) {
        #pragma unroll 8
        for (int c = 0; c < CN; c++) {
            float2 v = *(const float2*)(xb + (size_t)c*NN);
            float4 a = *(const float4*)(sa + c*4);
            d00 += a.x*v.x; d01 += a.x*v.y;
            d10 += a.y*v.x; d11 += a.y*v.y;
            d20 += a.z*v.x; d21 += a.z*v.y;
            d30 += a.w*v.x; d31 += a.w*v.y;
            sx0 += v.x; sx1 += v.y; ss0 += v.x*v.x; ss1 += v.y*v.y;
        }
    } else {
        #pragma unroll 8
        for (int c = 0; c < CN; c++) {
            float2 v = *(const float2*)(xb + (size_t)c*NN);
            float4 a = *(const float4*)(sa + c*4);
            d00 += a.x*v.x; d01 += a.x*v.y;
            d10 += a.y*v.x; d11 += a.y*v.y;
            d20 += a.z*v.x; d21 += a.z*v.y;
            d30 += a.w*v.x; d31 += a.w*v.y;
        }
    }

    float m0, m1, r0, r1;
    int n = n0 + 2*tid;
    if (first) {
        m0 = sx0 * (1.0f/CN); m1 = sx1 * (1.0f/CN);
        float v0 = ss0 * (1.0f/CN) - m0*m0;
        float v1 = ss1 * (1.0f/CN) - m1*m1;
        r0 = rsqrtf(v0 + 1e-5f); r1 = rsqrtf(v1 + 1e-5f);
        *(float2*)(g_mean + b*NN + n) = make_float2(m0, m1);
        *(float2*)(g_rstd + b*NN + n) = make_float2(r0, r1);
    } else {
        float2 mm = *(const float2*)(g_mean + b*NN + n);
        float2 rr = *(const float2*)(g_rstd + b*NN + n);
        m0 = mm.x; m1 = mm.y; r0 = rr.x; r1 = rr.y;
    }

    float G0 = sc[0], G1 = sc[1], G2 = sc[2], G3 = sc[3];
    float o0 = sc[4], o1 = sc[5], o2 = sc[6], o3 = sc[7];

    float Sk0, Sk1, Sk2, Sk3, Uk0, Uk1, Uk2, Uk3;
    {   // pixel 0
        float l0 = r0*(d00 - m0*G0) + o0;
        float l1 = r0*(d10 - m0*G1) + o1;
        float l2 = r0*(d20 - m0*G2) + o2;
        float l3 = r0*(d30 - m0*G3) + o3;
        float M = fmaxf(fmaxf(l0,l1), fmaxf(l2,l3));
        float e0 = __expf(l0-M), e1 = __expf(l1-M), e2 = __expf(l2-M), e3 = __expf(l3-M);
        float iz = 1.0f / (e0+e1+e2+e3);
        float a0 = e0*iz, a1 = e1*iz, a2 = e2*iz, a3 = e3*iz;
        st[0][2*tid] = a0*r0; st[1][2*tid] = a1*r0;
        st[2][2*tid] = a2*r0; st[3][2*tid] = a3*r0;
        Sk0 = a0; Sk1 = a1; Sk2 = a2; Sk3 = a3;
        float rm = r0*m0;
        Uk0 = a0*rm; Uk1 = a1*rm; Uk2 = a2*rm; Uk3 = a3*rm;
    }
    {   // pixel 1
        float l0 = r1*(d01 - m1*G0) + o0;
        float l1 = r1*(d11 - m1*G1) + o1;
        float l2 = r1*(d21 - m1*G2) + o2;
        float l3 = r1*(d31 - m1*G3) + o3;
        float M = fmaxf(fmaxf(l0,l1), fmaxf(l2,l3));
        float e0 = __expf(l0-M), e1 = __expf(l1-M), e2 = __expf(l2-M), e3 = __expf(l3-M);
        float iz = 1.0f / (e0+e1+e2+e3);
        float a0 = e0*iz, a1 = e1*iz, a2 = e2*iz, a3 = e3*iz;
        st[0][2*tid+1] = a0*r1; st[1][2*tid+1] = a1*r1;
        st[2][2*tid+1] = a2*r1; st[3][2*tid+1] = a3*r1;
        Sk0 += a0; Sk1 += a1; Sk2 += a2; Sk3 += a3;
        float rm = r1*m1;
        Uk0 += a0*rm; Uk1 += a1*rm; Uk2 += a2*rm; Uk3 += a3*rm;
    }
    #pragma unroll
    for (int o = 16; o; o >>= 1) {
        Sk0 += __shfl_down_sync(0xffffffffu, Sk0, o);
        Sk1 += __shfl_down_sync(0xffffffffu, Sk1, o);
        Sk2 += __shfl_down_sync(0xffffffffu, Sk2, o);
        Sk3 += __shfl_down_sync(0xffffffffu, Sk3, o);
        Uk0 += __shfl_down_sync(0xffffffffu, Uk0, o);
        Uk1 += __shfl_down_sync(0xffffffffu, Uk1, o);
        Uk2 += __shfl_down_sync(0xffffffffu, Uk2, o);
        Uk3 += __shfl_down_sync(0xffffffffu, Uk3, o);
    }
    if ((tid & 31) == 0) {
        atomicAdd(&g_S[b*4+0], Sk0); atomicAdd(&g_S[b*4+1], Sk1);
        atomicAdd(&g_S[b*4+2], Sk2); atomicAdd(&g_S[b*4+3], Sk3);
        atomicAdd(&g_U[b*4+0], Uk0); atomicAdd(&g_U[b*4+1], Uk1);
        atomicAdd(&g_U[b*4+2], Uk2); atomicAdd(&g_U[b*4+3], Uk3);
    }
    __syncthreads();

    // ---- phase 2: Araw[k,c] += sum_p t_k[p]*x[c,p]; warp <-> 32 channels ----
    {
        int w = tid >> 5, lane = tid & 31;
        // hoist t into registers: tr[k][j] covers pixels 4*(j*32+lane)..+3
        float4 tr[4][4];
        #pragma unroll
        for (int k = 0; k < 4; k++)
            #pragma unroll
            for (int j = 0; j < 4; j++)
                tr[k][j] = ((const float4*)st[k])[j*32 + lane];

        const float4* X4 = (const float4*)(x + (size_t)b*CN*NN + n0);
        #pragma unroll 2
        for (int cc = 0; cc < 32; cc++) {
            int c = w*32 + cc;
            const float4* xc = X4 + (size_t)c*(NN/4);
            float a0=0.f, a1=0.f, a2=0.f, a3=0.f;
            #pragma unroll
            for (int j = 0; j < 4; j++) {
                float4 xv = xc[j*32 + lane];
                a0 += xv.x*tr[0][j].x + xv.y*tr[0][j].y + xv.z*tr[0][j].z + xv.w*tr[0][j].w;
                a1 += xv.x*tr[1][j].x + xv.y*tr[1][j].y + xv.z*tr[1][j].z + xv.w*tr[1][j].w;
                a2 += xv.x*tr[2][j].x + xv.y*tr[2][j].y + xv.z*tr[2][j].z + xv.w*tr[2][j].w;
                a3 += xv.x*tr[3][j].x + xv.y*tr[3][j].y + xv.z*tr[3][j].z + xv.w*tr[3][j].w;
            }
            #pragma unroll
            for (int o = 16; o; o >>= 1) {
                a0 += __shfl_down_sync(0xffffffffu, a0, o);
                a1 += __shfl_down_sync(0xffffffffu, a1, o);
                a2 += __shfl_down_sync(0xffffffffu, a2, o);
                a3 += __shfl_down_sync(0xffffffffu, a3, o);
            }
            if (lane == 0) {
                atomicAdd(&g_Araw[(b*4+0)*CN + c], a0);
                atomicAdd(&g_Araw[(b*4+1)*CN + c], a1);
                atomicAdd(&g_Araw[(b*4+2)*CN + c], a2);
                atomicAdd(&g_Araw[(b*4+3)*CN + c], a3);
            }
        }
    }
}

// ---------------- updates = wx@Wv^T + sumw*bv  (chunked) -------------------
__global__ void __launch_bounds__(256) k_uv(
    const float* __restrict__ Wv, const float* __restrict__ bv,
    const float* __restrict__ lig, const float* __restrict__ lib)
{
    __shared__ __align__(16) float wx[4][256];
    __shared__ float sumw[4];
    int b = blockIdx.x, ch = blockIdx.y, tid = threadIdx.x;
    if (tid < 4) { float S = g_S[b*4+tid]; sumw[tid] = S / (S + 1e-8f); }
    float ligc = lig[tid], libc = lib[tid];
    #pragma unroll
    for (int k = 0; k < 4; k++) {
        float S = g_S[b*4+k], U = g_U[b*4+k];
        wx[k][tid] = (ligc*(g_Araw[(b*4+k)*CN + tid] - U) + libc*S) / (S + 1e-8f);
    }
    __syncthreads();

    int warp = tid >> 5, lane = tid & 31;
    #pragma unroll
    for (int j = 0; j < 8; j++) {
        int dd = ch*64 + warp*8 + j;
        const float4* w = (const float4*)(Wv + dd*CN + lane*8);
        float4 w0 = w[0], w1 = w[1];
        float acc[4];
        #pragma unroll
        for (int k = 0; k < 4; k++) {
            const float4* sk = (const float4*)&wx[k][lane*8];
            float4 a0 = sk[0], a1 = sk[1];
            acc[k] = w0.x*a0.x + w0.y*a0.y + w0.z*a0.z + w0.w*a0.w
                   + w1.x*a1.x + w1.y*a1.y + w1.z*a1.z + w1.w*a1.w;
        }
        #pragma unroll
        for (int o = 16; o; o >>= 1)
            #pragma unroll
            for (int k = 0; k < 4; k++)
                acc[k] += __shfl_down_sync(0xffffffffu, acc[k], o);
        if (lane == 0) {
            float bvd = bv[dd];
            #pragma unroll
            for (int k = 0; k < 4; k++)
                g_upd[(b*4+k)*CN + dd] = acc[k] + sumw[k]*bvd;
        }
    }
}

// ---------------- s1 = [prev|upd]@Wu^T + bu + prev  (chunked) ---------------
__global__ void __launch_bounds__(256) k_uu(
    const float* __restrict__ Wu, const float* __restrict__ bu)
{
    __shared__ __align__(16) float cat[4][512];
    int b = blockIdx.x, ch = blockIdx.y, tid = threadIdx.x;
    #pragma unroll
    for (int k = 0; k < 4; k++) {
        cat[k][tid]       = g_slots[(b*4+k)*CN + tid];
        cat[k][256 + tid] = g_upd  [(b*4+k)*CN + tid];
    }
    __syncthreads();

    int warp = tid >> 5, lane = tid & 31;
    #pragma unroll
    for (int j = 0; j < 8; j++) {
        int dd = ch*64 + warp*8 + j;
        const float4* w = (const float4*)(Wu + dd*512 + lane*16);
        float4 w0 = w[0], w1 = w[1], w2 = w[2], w3 = w[3];
        float acc[4];
        #pragma unroll
        for (int k = 0; k < 4; k++) {
            const float4* sk = (const float4*)&cat[k][lane*16];
            float4 a0 = sk[0], a1 = sk[1], a2 = sk[2], a3 = sk[3];
            acc[k] = w0.x*a0.x + w0.y*a0.y + w0.z*a0.z + w0.w*a0.w
                   + w1.x*a1.x + w1.y*a1.y + w1.z*a1.z + w1.w*a1.w
                   + w2.x*a2.x + w2.y*a2.y + w2.z*a2.z + w2.w*a2.w
                   + w3.x*a3.x + w3.y*a3.y + w3.z*a3.z + w3.w*a3.w;
        }
        #pragma unroll
        for (int o = 16; o; o >>= 1)
            #pragma unroll
            for (int k = 0; k < 4; k++)
                acc[k] += __shfl_down_sync(0xffffffffu, acc[k], o);
        if (lane == 0) {
            float bud = bu[dd];
            #pragma unroll
            for (int k = 0; k < 4; k++)
                g_s1[(b*4+k)*CN + dd] = acc[k] + bud + cat[k][dd];
        }
    }
}

// ---------------- h = gelu(LN(s1)@W1^T + b1)  (chunked) ---------------------
__global__ void __launch_bounds__(256) k_h(
    const float* __restrict__ W1, const float* __restrict__ b1,
    const float* __restrict__ lmg, const float* __restrict__ lmb)
{
    __shared__ __align__(16) float mln[4][256];
    __shared__ float red[16];
    int b = blockIdx.x, ch = blockIdx.y, tid = threadIdx.x;
    float lg = lmg[tid], lb = lmb[tid];
    #pragma unroll
    for (int k = 0; k < 4; k++) {
        float v = g_s1[(b*4+k)*CN + tid];
        float a = v, bb = v*v;
        blockReduce2(a, bb, red);
        float m = a * (1.0f/CN);
        float var = bb * (1.0f/CN) - m*m;
        float rs = rsqrtf(var + 1e-5f);
        mln[k][tid] = (v - m) * rs * lg + lb;
    }
    __syncthreads();

    int warp = tid >> 5, lane = tid & 31;
    #pragma unroll
    for (int j = 0; j < 8; j++) {
        int dd = ch*64 + warp*8 + j;
        const float4* w = (const float4*)(W1 + dd*CN + lane*8);
        float4 w0 = w[0], w1 = w[1];
        float acc[4];
        #pragma unroll
        for (int k = 0; k < 4; k++) {
            const float4* sk = (const float4*)&mln[k][lane*8];
            float4 a0 = sk[0], a1 = sk[1];
            acc[k] = w0.x*a0.x + w0.y*a0.y + w0.z*a0.z + w0.w*a0.w
                   + w1.x*a1.x + w1.y*a1.y + w1.z*a1.z + w1.w*a1.w;
        }
        #pragma unroll
        for (int o = 16; o; o >>= 1)
            #pragma unroll
            for (int k = 0; k < 4; k++)
                acc[k] += __shfl_down_sync(0xffffffffu, acc[k], o);
        if (lane == 0) {
            float bh = b1[dd];
            #pragma unroll
            for (int k = 0; k < 4; k++) {
                float h = acc[k] + bh;
                g_h[(b*4+k)*HN + dd] = h * normcdff(h);
            }
        }
    }
}

// ---------------- slots = s1 + h@W2^T + b2  (chunked); zero next accums -----
__global__ void __launch_bounds__(256) k_o(
    const float* __restrict__ W2, const float* __restrict__ b2,
    int final, float* __restrict__ out)
{
    __shared__ __align__(16) float hsm[4][512];
    int b = blockIdx.x, ch = blockIdx.y, tid = threadIdx.x;
    #pragma unroll
    for (int k = 0; k < 4; k++) {
        hsm[k][tid]       = g_h[(b*4+k)*HN + tid];
        hsm[k][256 + tid] = g_h[(b*4+k)*HN + 256 + tid];
    }
    __syncthreads();

    int warp = tid >> 5, lane = tid & 31;
    #pragma unroll
    for (int j = 0; j < 8; j++) {
        int dd = ch*64 + warp*8 + j;
        const float4* w = (const float4*)(W2 + dd*512 + lane*16);
        float4 w0 = w[0], w1 = w[1], w2 = w[2], w3 = w[3];
        float acc[4];
        #pragma unroll
        for (int k = 0; k < 4; k++) {
            const float4* sk = (const float4*)&hsm[k][lane*16];
            float4 a0 = sk[0], a1 = sk[1], a2 = sk[2], a3 = sk[3];
            acc[k] = w0.x*a0.x + w0.y*a0.y + w0.z*a0.z + w0.w*a0.w
                   + w1.x*a1.x + w1.y*a1.y + w1.z*a1.z + w1.w*a1.w
                   + w2.x*a2.x + w2.y*a2.y + w2.z*a2.z + w2.w*a2.w
                   + w3.x*a3.x + w3.y*a3.y + w3.z*a3.z + w3.w*a3.w;
        }
        #pragma unroll
        for (int o = 16; o; o >>= 1)
            #pragma unroll
            for (int k = 0; k < 4; k++)
                acc[k] += __shfl_down_sync(0xffffffffu, acc[k], o);
        if (lane == 0) {
            float b2d = b2[dd];
            #pragma unroll
            for (int k = 0; k < 4; k++) {
                float o_ = acc[k] + b2d + g_s1[(b*4+k)*CN + dd];
                g_slots[(b*4+k)*CN + dd] = o_;
                if (final) out[(b*4+k)*CN + dd] = o_;
            }
        }
    }

    int kk = tid >> 6, cl = tid & 63;
    g_Araw[(b*4+kk)*CN + ch*64 + cl] = 0.f;
    if (ch == 0 && tid < 4) {
        g_S[b*4+tid] = 0.f; g_U[b*4+tid] = 0.f;
        g_G[b*4+tid] = 0.f; g_off[b*4+tid] = 0.f;
    }
}

// ---------------- final head ----------------
__global__ void __launch_bounds__(256) k_f1(
    const float* __restrict__ We1, const float* __restrict__ be1,
    const float* __restrict__ We2)
{
    __shared__ __align__(16) float sl[4][256];
    int b = blockIdx.x, ch = blockIdx.y, tid = threadIdx.x;
    #pragma unroll
    for (int k = 0; k < 4; k++) sl[k][tid] = g_slots[(b*4+k)*CN + tid];
    __syncthreads();

    int warp = tid >> 5, lane = tid & 31;
    float zp[4] = {0,0,0,0};
    #pragma unroll
    for (int j = 0; j < 8; j++) {
        int dd = ch*64 + warp*8 + j;
        const float4* w = (const float4*)(We1 + dd*CN + lane*8);
        float4 w0 = w[0], w1 = w[1];
        float acc[4];
        #pragma unroll
        for (int k = 0; k < 4; k++) {
            const float4* sk = (const float4*)&sl[k][lane*8];
            float4 a0 = sk[0], a1 = sk[1];
            acc[k] = w0.x*a0.x + w0.y*a0.y + w0.z*a0.z + w0.w*a0.w
                   + w1.x*a1.x + w1.y*a1.y + w1.z*a1.z + w1.w*a1.w;
        }
        #pragma unroll
        for (int o = 16; o; o >>= 1)
            #pragma unroll
            for (int k = 0; k < 4; k++)
                acc[k] += __shfl_down_sync(0xffffffffu, acc[k], o);
        if (lane == 0) {
            float bed = be1[dd], wed = We2[dd];
            #pragma unroll
            for (int k = 0; k < 4; k++) {
                float e = acc[k] + bed;
                zp[k] += (e * normcdff(e)) * wed;
            }
        }
    }
    if (lane == 0) {
        #pragma unroll
        for (int k = 0; k < 4; k++) atomicAdd(&g_z[b*4+k], zp[k]);
    }
}

__global__ void k_f2(const float* __restrict__ be2, float* __restrict__ out, int out_size) {
    int r = threadIdx.x;
    if (out_size > BN*KN*CN) {
        float z = g_z[r] + be2[0];
        out[BN*KN*CN + r] = 1.0f / (1.0f + __expf(-z));
    }
}

// ---------------- launch ----------------
extern "C" void kernel_launch(void* const* d_in, const int* in_sizes, int n_in,
                              void* d_out, int out_size) {
    (void)in_sizes; (void)n_in;
    const float* x    = (const float*)d_in[0];
    const float* noise= (const float*)d_in[1];
    const float* mu   = (const float*)d_in[2];
    const float* lsig = (const float*)d_in[3];
    const float* lig  = (const float*)d_in[4];
    const float* lib  = (const float*)d_in[5];
    const float* lsg  = (const float*)d_in[6];
    const float* lsb  = (const float*)d_in[7];
    const float* lmg  = (const float*)d_in[8];
    const float* lmb  = (const float*)d_in[9];
    const float* Wq   = (const float*)d_in[10];
    const float* bq   = (const float*)d_in[11];
    const float* Wk   = (const float*)d_in[12];
    const float* bk   = (const float*)d_in[13];
    const float* Wv   = (const float*)d_in[14];
    const float* bv   = (const float*)d_in[15];
    const float* Wu   = (const float*)d_in[16];
    const float* bu   = (const float*)d_in[17];
    const float* W1   = (const float*)d_in[18];
    const float* b1   = (const float*)d_in[19];
    const float* W2   = (const float*)d_in[20];
    const float* b2   = (const float*)d_in[21];
    const float* We1  = (const float*)d_in[22];
    const float* be1  = (const float*)d_in[23];
    const float* We2  = (const float*)d_in[24];
    const float* be2  = (const float*)d_in[25];

    k_init<<<BN*KN, CN>>>(noise, mu, lsig);
    for (int it = 0; it < 3; it++) {
        k_q<<<dim3(16,4), 256>>>(Wq, bq, bk, lsg, lsb);
        k_a<<<dim3(16,4), 256>>>(Wk, lig, lib);
        k_attn<<<dim3(16,8), 256>>>(x, it == 0 ? 1 : 0);
        k_uv<<<dim3(16,4), 256>>>(Wv, bv, lig, lib);
        k_uu<<<dim3(16,4), 256>>>(Wu, bu);
        k_h <<<dim3(16,8), 256>>>(W1, b1, lmg, lmb);
        k_o <<<dim3(16,4), 256>>>(W2, b2, it == 2 ? 1 : 0, (float*)d_out);
    }
    k_f1<<<dim3(16,2), 256>>>(We1, be1, We2);
    k_f2<<<1, 64>>>(be2, (float*)d_out, out_size);
}